// round 16
// baseline (speedup 1.0000x reference)
#include <cuda_runtime.h>
#include <cuda_fp16.h>
#include <math.h>
#include <stdint.h>

#define T_ 8
#define N_ 10000
#define E_ 320000
#define H_ 4
#define NCOM_ 100

// ===== scratch =====
__device__ int   g_is64;
__device__ __align__(16) __half g_h1h[(size_t)T_ * N_ * 128];
__device__ __align__(16) __half g_h2h[(size_t)T_ * N_ * 64];
__device__ __align__(16) __half g_f[(size_t)T_ * N_ * 128];
__device__ __align__(16) float g_as[T_ * N_ * H_];
__device__ __align__(16) float g_ad[T_ * N_ * H_];
__device__ int   g_src[T_ * E_];
__device__ int   g_dst[T_ * E_];
__device__ int   g_cnt[T_ * N_];
__device__ int   g_rowptr[T_ * (N_ + 1)];
__device__ int   g_cursor[T_ * N_];
__device__ int   g_sorted[T_ * E_];
__device__ float g_comnum[T_ * NCOM_ * 64];
__device__ float g_comden[T_ * NCOM_];
__device__ __align__(16) __half g_Zx[(size_t)T_ * N_ * 512];
__device__ __align__(16) float g_cbuf[N_ * 128];
__device__ __align__(16) float g_dec[N_ * 128];
__device__ float g_colsq[64];
__device__ __align__(16) __half g_hb0[N_ * 128];
__device__ __align__(16) __half g_hb1[N_ * 128];
__device__ __align__(16) __half g_pa[(size_t)N_ * 160];
__device__ __align__(16) __half g_pb[(size_t)N_ * 160];
__device__ __align__(16) __half g_wt[512 * 128];

// ===== helpers =====
__device__ __forceinline__ long long ld_idx(const void* p, size_t i) {
    if (g_is64) return ((const long long*)p)[i];
    return (long long)((const int*)p)[i];
}
__device__ __forceinline__ float sigf(float x) { return 1.f / (1.f + expf(-x)); }
__device__ __forceinline__ float sigf_fast(float x) {
    return __fdividef(1.f, 1.f + __expf(-x));
}
__device__ __forceinline__ float tanh_fast(float x) {
    float e = __expf(2.f * x);
    return 1.f - __fdividef(2.f, e + 1.f);
}
__device__ __forceinline__ float tanh_hw(float x) {
    float y;
    asm("tanh.approx.f32 %0, %1;" : "=f"(y) : "f"(x));
    return y;
}
__device__ __forceinline__ float one_p_tanh(float x) {
    float ax = fabsf(x);
    if (ax < 0.15f) {
        float x2 = x * x;
        return fmaf(x, fmaf(x2, -0.33333333f, 1.f), 1.f);
    }
    return 1.f + tanh_hw(x);
}
__device__ __forceinline__ void mma_f16(float* c, uint32_t a0, uint32_t a1, uint32_t a2,
                                        uint32_t a3, uint32_t b0, uint32_t b1) {
    asm volatile(
        "mma.sync.aligned.m16n8k16.row.col.f32.f16.f16.f32 "
        "{%0,%1,%2,%3}, {%4,%5,%6,%7}, {%8,%9}, {%0,%1,%2,%3};"
        : "+f"(c[0]), "+f"(c[1]), "+f"(c[2]), "+f"(c[3])
        : "r"(a0), "r"(a1), "r"(a2), "r"(a3), "r"(b0), "r"(b1));
}

__global__ void detect64_kernel(const int* ei32) {
    int ok = 1;
    for (int i = 1; i < 64; i += 2)
        if (ei32[i] != 0) ok = 0;
    g_is64 = ok;
}
// decode edge_index into int32 src/dst
__global__ void decode_edges(const void* ei) {
    int idx = blockIdx.x * blockDim.x + threadIdx.x;
    if (idx >= T_ * E_) return;
    int t = idx / E_, e = idx - t * E_;
    g_src[idx] = (int)ld_idx(ei, (size_t)t * 2 * E_ + e);
    g_dst[idx] = (int)ld_idx(ei, (size_t)t * 2 * E_ + E_ + e);
}
__global__ void fill_f(float* p, float v, int n) {
    int i = blockIdx.x * blockDim.x + threadIdx.x;
    if (i < n) p[i] = v;
}
__global__ void fill_i(int* p, int v, int n) {
    int i = blockIdx.x * blockDim.x + threadIdx.x;
    if (i < n) p[i] = v;
}
__global__ void meso_zero() {
    int i = blockIdx.x * blockDim.x + threadIdx.x;
    if (i < T_ * NCOM_ * 64) g_comnum[i] = 0.f;
    if (i < T_ * NCOM_) g_comden[i] = 0.f;
}
__global__ void cvt16(const float4* __restrict__ x, __half2* __restrict__ y, int n4) {
    int i = blockIdx.x * blockDim.x + threadIdx.x;
    if (i >= n4) return;
    float4 v = x[i];
    y[2 * i]     = __floats2half2_rn(v.x, v.y);
    y[2 * i + 1] = __floats2half2_rn(v.z, v.w);
}
__global__ void wsplit16(const float* __restrict__ B, __half* __restrict__ bt, int Dn) {
    int idx = blockIdx.x * blockDim.x + threadIdx.x;
    if (idx >= Dn * 128) return;
    int n = idx >> 7, k = idx & 127;
    bt[idx] = __float2half(B[(size_t)k * Dn + n]);
}
// gate-interleaved permute for LSTM weights: p = (j/8)*32 + gate*8 + j%8
__global__ void wsplit16_lstm(const float* __restrict__ B, __half* __restrict__ bt) {
    int idx = blockIdx.x * blockDim.x + threadIdx.x;
    if (idx >= 512 * 128) return;
    int p = idx >> 7, k = idx & 127;
    int blk = p >> 5, r = p & 31, gate = r >> 3, jl = r & 7;
    int o = gate * 128 + blk * 8 + jl;
    bt[idx] = __float2half(B[(size_t)k * 512 + o]);
}

// ===== smem tile copy =====
template <int KU4, int SU4, int THREADS>
__device__ __forceinline__ void cp16(const uint4* __restrict__ G, char* sm, int off,
                                     int base, int Mlim, int tid, int rows) {
    int total = rows * KU4;
    for (int idx = tid; idx < total; idx += THREADS) {
        int row = idx / KU4, c = idx - row * KU4;
        uint4 v = make_uint4(0, 0, 0, 0);
        if (base + row < Mlim) v = G[(size_t)(base + row) * KU4 + c];
        ((uint4*)(sm + off))[row * SU4 + c] = v;
    }
}

// ===== fp16 MMA GEMM: CTA 128x64, 256 threads =====
#define SM_B 34816
#define MG_SMEM 52736

#define GEMM_MAINLOOP(ACC)                                                         \
    int ra0 = (wr * 32 + g) * 68;                                                  \
    int rb0 = ra0 + 8 * 68, ra1 = ra0 + 16 * 68, rb1 = ra0 + 24 * 68;              \
    _Pragma("unroll")                                                              \
    for (int kc = 0; kc < 8; kc++) {                                               \
        int ka = kc * 8 + tq;                                                      \
        uint32_t a00 = SA[ra0 + ka], a01 = SA[rb0 + ka];                           \
        uint32_t a02 = SA[ra0 + ka + 4], a03 = SA[rb0 + ka + 4];                   \
        uint32_t a10 = SA[ra1 + ka], a11 = SA[rb1 + ka];                           \
        uint32_t a12 = SA[ra1 + ka + 4], a13 = SA[rb1 + ka + 4];                   \
        _Pragma("unroll")                                                          \
        for (int nb = 0; nb < 4; nb++) {                                           \
            int nr = (wc * 32 + nb * 8 + g) * 68;                                  \
            uint32_t b0 = SB[nr + ka], b1 = SB[nr + ka + 4];                       \
            mma_f16(ACC[0][nb], a00, a01, a02, a03, b0, b1);                       \
            mma_f16(ACC[1][nb], a10, a11, a12, a13, b0, b1);                       \
        }                                                                          \
    }

// mode: 0 = store fp32, 2 = store fp16
__global__ __launch_bounds__(256, 3) void mma_gemm(
    const __half* __restrict__ A, const __half* __restrict__ B,
    void* __restrict__ Cv, int M, int Dn,
    long long sA, long long sC, int mode)
{
    extern __shared__ char sm[];
    int tid = threadIdx.x, w = tid >> 5, lane = tid & 31;
    int g = lane >> 2, tq = lane & 3;
    int wr = w >> 1, wc = w & 1;
    int m0 = blockIdx.x * 128, n0 = blockIdx.y * 64, t = blockIdx.z;
    A += (size_t)t * sA;

    cp16<16, 17, 256>((const uint4*)A, sm, 0, m0, M, tid, 128);
    cp16<16, 17, 256>((const uint4*)B, sm, SM_B, n0, Dn, tid, 64);
    __syncthreads();

    const uint32_t* SA = (const uint32_t*)sm;
    const uint32_t* SB = (const uint32_t*)(sm + SM_B);

    float acc[2][4][4];
#pragma unroll
    for (int rg = 0; rg < 2; rg++)
#pragma unroll
        for (int nb = 0; nb < 4; nb++)
#pragma unroll
            for (int q = 0; q < 4; q++) acc[rg][nb][q] = 0.f;

    GEMM_MAINLOOP(acc)

#pragma unroll
    for (int rg = 0; rg < 2; rg++) {
        int r0 = m0 + wr * 32 + rg * 16 + g, r1 = r0 + 8;
#pragma unroll
        for (int nb = 0; nb < 4; nb++) {
            int col = n0 + wc * 32 + nb * 8 + 2 * tq;
            if (mode == 2) {
                __half* Ch = (__half*)Cv + (size_t)t * sC;
                if (r0 < M)
                    *(__half2*)(Ch + (size_t)r0 * Dn + col) = __floats2half2_rn(acc[rg][nb][0], acc[rg][nb][1]);
                if (r1 < M)
                    *(__half2*)(Ch + (size_t)r1 * Dn + col) = __floats2half2_rn(acc[rg][nb][2], acc[rg][nb][3]);
            } else {
                float* C = (float*)Cv + (size_t)t * sC;
                if (r0 < M)
                    *(float2*)(C + (size_t)r0 * Dn + col) = make_float2(acc[rg][nb][0], acc[rg][nb][1]);
                if (r1 < M)
                    *(float2*)(C + (size_t)r1 * Dn + col) = make_float2(acc[rg][nb][2], acc[rg][nb][3]);
            }
        }
    }
}

// ===== fp16 MMA GEMM: CTA 128x128, 512 threads (Dn >= 128) =====
#define SM_B2 34816
#define MG2_SMEM 69632

__global__ __launch_bounds__(512, 2) void mma_gemm_128(
    const __half* __restrict__ A, const __half* __restrict__ B,
    void* __restrict__ Cv, int M, int Dn,
    long long sA, long long sC, int mode)
{
    extern __shared__ char sm[];
    int tid = threadIdx.x, w = tid >> 5, lane = tid & 31;
    int g = lane >> 2, tq = lane & 3;
    int wr = w >> 2, wc = w & 3;
    int m0 = blockIdx.x * 128, n0 = blockIdx.y * 128, t = blockIdx.z;
    A += (size_t)t * sA;

    cp16<16, 17, 512>((const uint4*)A, sm, 0, m0, M, tid, 128);
    cp16<16, 17, 512>((const uint4*)B, sm, SM_B2, n0, Dn, tid, 128);
    __syncthreads();

    const uint32_t* SA = (const uint32_t*)sm;
    const uint32_t* SB = (const uint32_t*)(sm + SM_B2);

    float acc[2][4][4];
#pragma unroll
    for (int rg = 0; rg < 2; rg++)
#pragma unroll
        for (int nb = 0; nb < 4; nb++)
#pragma unroll
            for (int q = 0; q < 4; q++) acc[rg][nb][q] = 0.f;

    GEMM_MAINLOOP(acc)

#pragma unroll
    for (int rg = 0; rg < 2; rg++) {
        int r0 = m0 + wr * 32 + rg * 16 + g, r1 = r0 + 8;
#pragma unroll
        for (int nb = 0; nb < 4; nb++) {
            int col = n0 + wc * 32 + nb * 8 + 2 * tq;
            if (mode == 2) {
                __half* Ch = (__half*)Cv + (size_t)t * sC;
                if (r0 < M)
                    *(__half2*)(Ch + (size_t)r0 * Dn + col) = __floats2half2_rn(acc[rg][nb][0], acc[rg][nb][1]);
                if (r1 < M)
                    *(__half2*)(Ch + (size_t)r1 * Dn + col) = __floats2half2_rn(acc[rg][nb][2], acc[rg][nb][3]);
            } else {
                float* C = (float*)Cv + (size_t)t * sC;
                if (r0 < M)
                    *(float2*)(C + (size_t)r0 * Dn + col) = make_float2(acc[rg][nb][0], acc[rg][nb][1]);
                if (r1 < M)
                    *(float2*)(C + (size_t)r1 * Dn + col) = make_float2(acc[rg][nb][2], acc[rg][nb][3]);
            }
        }
    }
}

// ===== fused LSTM GEMM (128x128 tile): z = Zx(fp16) + Wh*h (+b) =====
__global__ __launch_bounds__(512, 2) void mma_gemm_lstm(
    const __half* __restrict__ A, const __half* __restrict__ B,
    const __half* __restrict__ Zt, const float* __restrict__ bias,
    __half* __restrict__ hout)
{
    extern __shared__ char sm[];
    int tid = threadIdx.x, w = tid >> 5, lane = tid & 31;
    int g = lane >> 2, tq = lane & 3;
    int wr = w >> 2, wc = w & 3;
    int m0 = blockIdx.x * 128, n0 = blockIdx.y * 128;

    cp16<16, 17, 512>((const uint4*)A, sm, 0, m0, N_, tid, 128);
    cp16<16, 17, 512>((const uint4*)B, sm, SM_B2, n0, 512, tid, 128);
    __syncthreads();

    const uint32_t* SA = (const uint32_t*)sm;
    const uint32_t* SB = (const uint32_t*)(sm + SM_B2);

    float acc[2][4][4];
#pragma unroll
    for (int rg = 0; rg < 2; rg++)
#pragma unroll
        for (int nb = 0; nb < 4; nb++)
#pragma unroll
            for (int q = 0; q < 4; q++) acc[rg][nb][q] = 0.f;

    GEMM_MAINLOOP(acc)

    int pbase = n0 + wc * 32;
    int jb8 = (pbase >> 5) * 8;
    float bi[2], bf[2], bg[2], bo[2];
#pragma unroll
    for (int q01 = 0; q01 < 2; q01++) {
        int j = jb8 + 2 * tq + q01;
        bi[q01] = bias[j];
        bf[q01] = bias[128 + j];
        bg[q01] = bias[256 + j];
        bo[q01] = bias[384 + j];
    }
#pragma unroll
    for (int rg = 0; rg < 2; rg++) {
#pragma unroll
        for (int rr = 0; rr < 2; rr++) {
            int row = m0 + wr * 32 + rg * 16 + g + rr * 8;
            if (row >= N_) continue;
            int qoff = rr * 2;
            float hv[2], cv[2];
#pragma unroll
            for (int q01 = 0; q01 < 2; q01++) {
                int j = jb8 + 2 * tq + q01;
                const __half* zr = Zt + (size_t)row * 512 + pbase + 2 * tq + q01;
                float zi = acc[rg][0][qoff + q01] + __half2float(zr[0])  + bi[q01];
                float zf = acc[rg][1][qoff + q01] + __half2float(zr[8])  + bf[q01];
                float zg = acc[rg][2][qoff + q01] + __half2float(zr[16]) + bg[q01];
                float zo = acc[rg][3][qoff + q01] + __half2float(zr[24]) + bo[q01];
                float c = sigf_fast(zf) * g_cbuf[row * 128 + j] + sigf_fast(zi) * tanh_fast(zg);
                cv[q01] = c;
                hv[q01] = sigf_fast(zo) * tanh_fast(c);
            }
            int j0 = jb8 + 2 * tq;
            *(float2*)&g_cbuf[row * 128 + j0] = make_float2(cv[0], cv[1]);
            *(__half2*)&hout[row * 128 + j0] = __floats2half2_rn(hv[0], hv[1]);
        }
    }
}

// t=0 LSTM (c0 = 0)
__global__ void lstm_pw0(const float* __restrict__ b, __half* __restrict__ hout) {
    int idx = blockIdx.x * blockDim.x + threadIdx.x;
    if (idx >= N_ * 128) return;
    int n = idx >> 7, j = idx & 127;
    const __half* z = g_Zx + (size_t)n * 512 + (j >> 3) * 32 + (j & 7);
    float zi = __half2float(z[0]) + b[j];
    float zg = __half2float(z[16]) + b[256 + j];
    float zo = __half2float(z[24]) + b[384 + j];
    float c = sigf_fast(zi) * tanh_fast(zg);
    g_cbuf[idx] = c;
    hout[idx] = __float2half(sigf_fast(zo) * tanh_fast(c));
}

// ===== pairwise: CTA 128x128, 512 threads, K=160, streaming stores =====
#define PW_B 43008
#define PW_SMEM 86016

__global__ __launch_bounds__(512, 2) void pairwise_mma(float* __restrict__ out) {
    int bi = blockIdx.y, bj = blockIdx.x;
    if (bj < bi) return;
    int i0 = bi * 128, j0 = bj * 128;
    extern __shared__ char sm[];
    int tid = threadIdx.x, w = tid >> 5, lane = tid & 31;
    int g = lane >> 2, tq = lane & 3;
    int wr = w >> 2, wc = w & 3;

    cp16<20, 21, 512>((const uint4*)g_pa, sm, 0, i0, N_, tid, 128);
    cp16<20, 21, 512>((const uint4*)g_pb, sm, PW_B, j0, N_, tid, 128);
    __syncthreads();

    const uint32_t* SA = (const uint32_t*)sm;
    const uint32_t* SB = (const uint32_t*)(sm + PW_B);

    float accG[2][4][4], accS[2][4][4];
#pragma unroll
    for (int rg = 0; rg < 2; rg++)
#pragma unroll
        for (int nb = 0; nb < 4; nb++)
#pragma unroll
            for (int q = 0; q < 4; q++) { accG[rg][nb][q] = 0.f; accS[rg][nb][q] = 0.f; }

    int ra0 = (wr * 32 + g) * 84;
    int rb0 = ra0 + 8 * 84, ra1 = ra0 + 16 * 84, rb1 = ra0 + 24 * 84;
#pragma unroll
    for (int kc = 0; kc < 9; kc++) {
        int ka = kc * 8 + tq;
        uint32_t a00 = SA[ra0 + ka], a01 = SA[rb0 + ka];
        uint32_t a02 = SA[ra0 + ka + 4], a03 = SA[rb0 + ka + 4];
        uint32_t a10 = SA[ra1 + ka], a11 = SA[rb1 + ka];
        uint32_t a12 = SA[ra1 + ka + 4], a13 = SA[rb1 + ka + 4];
        float (*a0)[4] = (kc < 5) ? accG[0] : accS[0];
        float (*a1)[4] = (kc < 5) ? accG[1] : accS[1];
#pragma unroll
        for (int nb = 0; nb < 4; nb++) {
            int nr = (wc * 32 + nb * 8 + g) * 84;
            uint32_t b0 = SB[nr + ka], b1 = SB[nr + ka + 4];
            mma_f16(a0[nb], a00, a01, a02, a03, b0, b1);
            mma_f16(a1[nb], a10, a11, a12, a13, b0, b1);
        }
    }

    bool full = (i0 + 128 <= N_) && (j0 + 128 <= N_);
    float vv[2][4][4];
#pragma unroll
    for (int rg = 0; rg < 2; rg++) {
        int lr0 = wr * 32 + rg * 16 + g, lr1 = lr0 + 8;
        int ir0 = i0 + lr0, ir1 = i0 + lr1;
#pragma unroll
        for (int nb = 0; nb < 4; nb++) {
            int c0 = wc * 32 + nb * 8 + 2 * tq;
            vv[rg][nb][0] = one_p_tanh(accG[rg][nb][0] * accS[rg][nb][0]);
            vv[rg][nb][1] = one_p_tanh(accG[rg][nb][1] * accS[rg][nb][1]);
            vv[rg][nb][2] = one_p_tanh(accG[rg][nb][2] * accS[rg][nb][2]);
            vv[rg][nb][3] = one_p_tanh(accG[rg][nb][3] * accS[rg][nb][3]);
            if (full) {
                __stcs((float2*)(out + (size_t)ir0 * N_ + j0 + c0),
                       make_float2(vv[rg][nb][0], vv[rg][nb][1]));
                __stcs((float2*)(out + (size_t)ir1 * N_ + j0 + c0),
                       make_float2(vv[rg][nb][2], vv[rg][nb][3]));
            } else {
                if (ir0 < N_) {
                    if (j0 + c0 < N_)     __stcs(out + (size_t)ir0 * N_ + j0 + c0, vv[rg][nb][0]);
                    if (j0 + c0 + 1 < N_) __stcs(out + (size_t)ir0 * N_ + j0 + c0 + 1, vv[rg][nb][1]);
                }
                if (ir1 < N_) {
                    if (j0 + c0 < N_)     __stcs(out + (size_t)ir1 * N_ + j0 + c0, vv[rg][nb][2]);
                    if (j0 + c0 + 1 < N_) __stcs(out + (size_t)ir1 * N_ + j0 + c0 + 1, vv[rg][nb][3]);
                }
            }
        }
    }

    __syncthreads();
    float* vT = (float*)sm;  // [128][129]
#pragma unroll
    for (int rg = 0; rg < 2; rg++) {
        int lr0 = wr * 32 + rg * 16 + g, lr1 = lr0 + 8;
#pragma unroll
        for (int nb = 0; nb < 4; nb++) {
            int c0 = wc * 32 + nb * 8 + 2 * tq, c1 = c0 + 1;
            vT[c0 * 129 + lr0] = vv[rg][nb][0];
            vT[c1 * 129 + lr0] = vv[rg][nb][1];
            vT[c0 * 129 + lr1] = vv[rg][nb][2];
            vT[c1 * 129 + lr1] = vv[rg][nb][3];
        }
    }
    __syncthreads();
    for (int idx = tid; idx < 128 * 128; idx += 512) {
        int r2 = idx >> 7, c2 = idx & 127;
        int jj = j0 + r2, ii = i0 + c2;
        if (jj > ii && jj < N_ && ii < N_) __stcs(out + (size_t)jj * N_ + ii, vT[r2 * 129 + c2]);
    }
}

// ===== GAT kernels =====
__global__ void alpha_kernel(const __half* __restrict__ h, const float* __restrict__ a_s,
                             const float* __restrict__ a_d, int dh) {
    int idx = blockIdx.x * blockDim.x + threadIdx.x;
    if (idx >= T_ * N_ * H_) return;
    int hh = idx & 3, tn = idx >> 2;
    const __half2* hr = (const __half2*)(h + (size_t)tn * (H_ * dh) + hh * dh);
    float s = 0.f, d = 0.f;
    for (int k = 0; k < dh / 2; k++) {
        float2 v = __half22float2(hr[k]);
        s += v.x * a_s[hh * dh + 2 * k] + v.y * a_s[hh * dh + 2 * k + 1];
        d += v.x * a_d[hh * dh + 2 * k] + v.y * a_d[hh * dh + 2 * k + 1];
    }
    g_as[idx] = s; g_ad[idx] = d;
}
__global__ void csr_count() {
    int idx = blockIdx.x * blockDim.x + threadIdx.x;
    if (idx >= T_ * E_) return;
    int t = idx / E_;
    atomicAdd(&g_cnt[t * N_ + g_dst[idx]], 1);
}
// warp-shuffle scan; also initializes cursor = row start
__global__ void csr_scan() {
    int t = blockIdx.x, tid = threadIdx.x;
    int lane = tid & 31, wid = tid >> 5;
    __shared__ int wsum[32];
    int off = 0;
    for (int chunk = 0; chunk < N_; chunk += 1024) {
        int i = chunk + tid;
        int v = (i < N_) ? g_cnt[t * N_ + i] : 0;
        int s = v;
#pragma unroll
        for (int o = 1; o < 32; o <<= 1) {
            int x = __shfl_up_sync(0xffffffffu, s, o);
            if (lane >= o) s += x;
        }
        if (lane == 31) wsum[wid] = s;
        __syncthreads();
        if (wid == 0) {
            int ws = wsum[lane];
#pragma unroll
            for (int o = 1; o < 32; o <<= 1) {
                int x = __shfl_up_sync(0xffffffffu, ws, o);
                if (lane >= o) ws += x;
            }
            wsum[lane] = ws;
        }
        __syncthreads();
        int base = off + (wid > 0 ? wsum[wid - 1] : 0);
        if (i < N_) {
            int start = base + s - v;
            g_rowptr[t * (N_ + 1) + i] = start;
            g_cursor[t * N_ + i] = start;
        }
        off += wsum[31];
        __syncthreads();
    }
    if (tid == 0) g_rowptr[t * (N_ + 1) + N_] = off;
}
__global__ void csr_scatter() {
    int idx = blockIdx.x * blockDim.x + threadIdx.x;
    if (idx >= T_ * E_) return;
    int t = idx / E_, e = idx - t * E_;
    int pos = atomicAdd(&g_cursor[t * N_ + g_dst[idx]], 1);
    g_sorted[t * E_ + pos] = e;
}

// fused gather: THREADS threads, each owns 2 adjacent columns (half2)
template <int THREADS, int COLS, int DHEAD>
__global__ void gat_gather(const float* __restrict__ ew,
                           const __half* __restrict__ hsrc, __half* __restrict__ oh) {
    int t = blockIdx.y, n = blockIdx.x, tid = threadIdx.x;
    int start = g_rowptr[t * (N_ + 1) + n];
    int end = g_rowptr[t * (N_ + 1) + n + 1];
    int head = (2 * tid) / DHEAD;
    __shared__ int s_src[64];
    __shared__ float s_ex[64][4];
    float4 ad4 = *(const float4*)&g_ad[(t * N_ + n) * 4];
    float accx = 0.f, accy = 0.f, den = 0.f;
    for (int base = start; base < end; base += 64) {
        int cnt = min(64, end - base);
        if (THREADS == 32) __syncwarp(); else __syncthreads();
        for (int i = tid; i < cnt; i += THREADS) {
            int eid = g_sorted[t * E_ + base + i];
            int src = g_src[t * E_ + eid];
            s_src[i] = src;
            float4 s4 = *(const float4*)&g_as[(t * N_ + src) * 4];
            float wv = ew[(size_t)t * E_ + eid];
            float e0 = s4.x + ad4.x; e0 = e0 > 0.f ? e0 : 0.2f * e0;
            float e1 = s4.y + ad4.y; e1 = e1 > 0.f ? e1 : 0.2f * e1;
            float e2 = s4.z + ad4.z; e2 = e2 > 0.f ? e2 : 0.2f * e2;
            float e3 = s4.w + ad4.w; e3 = e3 > 0.f ? e3 : 0.2f * e3;
            s_ex[i][0] = __expf(e0) * wv;
            s_ex[i][1] = __expf(e1) * wv;
            s_ex[i][2] = __expf(e2) * wv;
            s_ex[i][3] = __expf(e3) * wv;
        }
        if (THREADS == 32) __syncwarp(); else __syncthreads();
#pragma unroll 8
        for (int i = 0; i < cnt; i++) {
            float exv = s_ex[i][head];
            den += exv;
            float2 hv = __half22float2(
                *(const __half2*)(hsrc + ((size_t)t * N_ + s_src[i]) * COLS + 2 * tid));
            accx = fmaf(exv, hv.x, accx);
            accy = fmaf(exv, hv.y, accy);
        }
    }
    float inv = __fdividef(1.f, den + 1e-16f);
    float vx = accx * inv, vy = accy * inv;
    vx = vx > 0.f ? vx : __expf(vx) - 1.f;
    vy = vy > 0.f ? vy : __expf(vy) - 1.f;
    *(__half2*)(oh + ((size_t)t * N_ + n) * 128 + 2 * tid) = __floats2half2_rn(vx, vy);
}

// ===== meso =====
#define MCHUNK 500
__global__ void meso_acc(const void* part, const float* __restrict__ Dw) {
    int t = blockIdx.y, c0 = blockIdx.x * MCHUNK, tid = threadIdx.x;
    __shared__ float sn[NCOM_ * 64];
    __shared__ float sd[NCOM_];
    __shared__ int sp[MCHUNK];
    __shared__ float sD[MCHUNK];
    for (int i = tid; i < NCOM_ * 64; i += blockDim.x) sn[i] = 0.f;
    for (int i = tid; i < NCOM_; i += blockDim.x) sd[i] = 0.f;
    int nmax = min(MCHUNK, N_ - c0);
    for (int i = tid; i < nmax; i += blockDim.x) {
        sp[i] = (int)ld_idx(part, (size_t)t * N_ + c0 + i);
        sD[i] = Dw[(size_t)t * N_ + c0 + i];
    }
    __syncthreads();
    for (int idx = tid; idx < nmax * 64; idx += blockDim.x) {
        int nl = idx >> 6, c = idx & 63;
        float g = __half2float(g_f[((size_t)t * N_ + c0 + nl) * 128 + c]);
        atomicAdd(&sn[sp[nl] * 64 + c], sD[nl] * g);
        if (c == 0) atomicAdd(&sd[sp[nl]], sD[nl]);
    }
    __syncthreads();
    for (int i = tid; i < NCOM_ * 64; i += blockDim.x)
        atomicAdd(&g_comnum[t * NCOM_ * 64 + i], sn[i]);
    for (int i = tid; i < NCOM_; i += blockDim.x)
        atomicAdd(&g_comden[t * NCOM_ + i], sd[i]);
}
__global__ void meso_scatter(const void* part, __half* __restrict__ oh) {
    int idx = blockIdx.x * blockDim.x + threadIdx.x;
    if (idx >= T_ * N_ * 64) return;
    int t = idx / (N_ * 64);
    int r = idx - t * N_ * 64;
    int n = r >> 6, c = r & 63;
    int p = (int)ld_idx(part, (size_t)t * N_ + n);
    float mean = g_comnum[(t * NCOM_ + p) * 64 + c] / (g_comden[t * NCOM_ + p] + 1e-16f);
    oh[((size_t)t * N_ + n) * 128 + 64 + c] = __float2half(mean);
}

// ===== decoder prep =====
__global__ void emb_tanh(const float* __restrict__ emb_b) {
    __shared__ float s[64];
    int tid = threadIdx.x;
    if (tid < 64) s[tid] = 0.f;
    __syncthreads();
    int idx = blockIdx.x * 256 + tid;
    if (idx < N_ * 64) {
        int n = idx >> 6, c = idx & 63;
        float v = tanhf(g_dec[n * 128 + c] + emb_b[c]);
        g_dec[n * 128 + c] = v;
        atomicAdd(&s[c], v * v);
    }
    __syncthreads();
    if (tid < 64) atomicAdd(&g_colsq[tid], s[tid]);
}
__global__ void build_P(const float* __restrict__ scal_b) {
    int n = blockIdx.x, c = threadIdx.x;
    float e = g_dec[n * 128 + c] * rsqrtf(g_colsq[c]);
    float s = sigf(g_dec[n * 128 + 64 + c] + scal_b[c]);
    float v = e * e;
#pragma unroll
    for (int o = 16; o; o >>= 1) v += __shfl_down_sync(0xffffffff, v, o);
    __shared__ float shm[2];
    if ((c & 31) == 0) shm[c >> 5] = v;
    __syncthreads();
    float sq = shm[0] + shm[1];
    size_t base = (size_t)n * 160;
    __half he = __float2half(1.41421356f * e);
    __half hs = __float2half(s);
    g_pa[base + c] = he;        g_pb[base + c] = he;
    g_pa[base + 80 + c] = hs;   g_pb[base + 80 + c] = hs;
    if (c < 16) {
        __half za = __float2half(0.f), zb = za;
        if (c == 0) { za = __float2half(sq);   zb = __float2half(-1.f); }
        if (c == 1) { za = __float2half(1.f);  zb = __float2half(-sq); }
        g_pa[base + 64 + c] = za;
        g_pb[base + 64 + c] = zb;
        g_pa[base + 144 + c] = __float2half(0.f);
        g_pb[base + 144 + c] = __float2half(0.f);
    }
}

// ===== host =====
extern "C" void kernel_launch(void* const* d_in, const int* in_sizes, int n_in,
                              void* d_out, int out_size) {
    const float* feat   = (const float*)d_in[0];
    const float* ew     = (const float*)d_in[1];
    const float* Dw     = (const float*)d_in[2];
    const float* W1     = (const float*)d_in[3];
    const float* a_s1   = (const float*)d_in[4];
    const float* a_d1   = (const float*)d_in[5];
    const float* W2     = (const float*)d_in[6];
    const float* a_s2   = (const float*)d_in[7];
    const float* a_d2   = (const float*)d_in[8];
    const float* Wx     = (const float*)d_in[9];
    const float* Wh     = (const float*)d_in[10];
    const float* b_lstm = (const float*)d_in[11];
    const float* embW   = (const float*)d_in[12];
    const float* embB   = (const float*)d_in[13];
    const float* scalW  = (const float*)d_in[14];
    const float* scalB  = (const float*)d_in[15];
    const void*  ei     = (const void*)d_in[16];
    const void*  part   = (const void*)d_in[17];
    float* out = (float*)d_out;

    cudaFuncSetAttribute(mma_gemm, cudaFuncAttributeMaxDynamicSharedMemorySize, MG_SMEM);
    cudaFuncSetAttribute(mma_gemm_128, cudaFuncAttributeMaxDynamicSharedMemorySize, MG2_SMEM);
    cudaFuncSetAttribute(mma_gemm_lstm, cudaFuncAttributeMaxDynamicSharedMemorySize, MG2_SMEM);
    cudaFuncSetAttribute(pairwise_mma, cudaFuncAttributeMaxDynamicSharedMemorySize, PW_SMEM);

    float *dec, *colsq;
    int *cnt;
    __half *h1h, *h2h, *f16, *hb0, *hb1, *wt, *Zx;
    cudaGetSymbolAddress((void**)&h1h, g_h1h);
    cudaGetSymbolAddress((void**)&h2h, g_h2h);
    cudaGetSymbolAddress((void**)&f16, g_f);
    cudaGetSymbolAddress((void**)&Zx, g_Zx);
    cudaGetSymbolAddress((void**)&dec, g_dec);
    cudaGetSymbolAddress((void**)&colsq, g_colsq);
    cudaGetSymbolAddress((void**)&cnt, g_cnt);
    cudaGetSymbolAddress((void**)&hb0, g_hb0);
    cudaGetSymbolAddress((void**)&hb1, g_hb1);
    cudaGetSymbolAddress((void**)&wt, g_wt);
    __half* hbuf[2] = {hb0, hb1};

    const int MT = 79;
    const int TE = T_ * E_;
    const int TNH = T_ * N_ * H_;
    const int NS4 = T_ * N_ * 128 / 4;

    detect64_kernel<<<1, 1>>>((const int*)ei);
    decode_edges<<<(TE + 255) / 256, 256>>>(ei);

    // GAT layer 1
    cvt16<<<(NS4 + 255) / 256, 256>>>((const float4*)feat, (__half2*)f16, NS4);
    wsplit16<<<(128 * 128 + 255) / 256, 256>>>(W1, wt, 128);
    mma_gemm_128<<<dim3(MT, 1, 8), 512, MG2_SMEM>>>(f16, wt, h1h, N_, 128,
                                                    (long long)N_ * 128, (long long)N_ * 128, 2);
    alpha_kernel<<<(TNH + 255) / 256, 256>>>(h1h, a_s1, a_d1, 32);

    fill_i<<<(T_ * N_ + 255) / 256, 256>>>(cnt, 0, T_ * N_);
    csr_count<<<(TE + 255) / 256, 256>>>();
    csr_scan<<<T_, 1024>>>();
    csr_scatter<<<(TE + 255) / 256, 256>>>();

    gat_gather<64, 128, 32><<<dim3(N_, T_), 64>>>(ew, h1h, f16);

    // GAT layer 2
    wsplit16<<<(64 * 128 + 255) / 256, 256>>>(W2, wt, 64);
    mma_gemm<<<dim3(MT, 1, 8), 256, MG_SMEM>>>(f16, wt, h2h, N_, 64,
                                               (long long)N_ * 128, (long long)N_ * 64, 2);
    alpha_kernel<<<(TNH + 255) / 256, 256>>>(h2h, a_s2, a_d2, 16);
    gat_gather<32, 64, 16><<<dim3(N_, T_), 32>>>(ew, h2h, f16);

    // meso
    meso_zero<<<(T_ * NCOM_ * 64 + 255) / 256, 256>>>();
    meso_acc<<<dim3((N_ + MCHUNK - 1) / MCHUNK, T_), 256>>>(part, Dw);
    meso_scatter<<<(T_ * N_ * 64 + 255) / 256, 256>>>(part, f16);

    // LSTM
    wsplit16_lstm<<<(512 * 128 + 255) / 256, 256>>>(Wx, wt);
    mma_gemm_128<<<dim3(MT, 4, 8), 512, MG2_SMEM>>>(f16, wt, Zx, N_, 512,
                                                    (long long)N_ * 128, (long long)N_ * 512, 2);
    wsplit16_lstm<<<(512 * 128 + 255) / 256, 256>>>(Wh, wt);
    lstm_pw0<<<(N_ * 128 + 255) / 256, 256>>>(b_lstm, hbuf[0]);
    for (int t = 1; t < T_; t++) {
        mma_gemm_lstm<<<dim3(MT, 4), 512, MG2_SMEM>>>(hbuf[(t - 1) & 1], wt,
                                                      Zx + (size_t)t * N_ * 512, b_lstm,
                                                      hbuf[t & 1]);
    }
    __half* hlast = hbuf[(T_ - 1) & 1];

    // decoder
    wsplit16<<<(64 * 128 + 255) / 256, 256>>>(embW, wt, 64);
    wsplit16<<<(64 * 128 + 255) / 256, 256>>>(scalW, wt + 64 * 128, 64);
    mma_gemm_128<<<dim3(MT, 1, 1), 512, MG2_SMEM>>>(hlast, wt, dec, N_, 128, 0, 0, 0);
    fill_f<<<1, 64>>>(colsq, 0.f, 64);
    emb_tanh<<<(N_ * 64 + 255) / 256, 256>>>(embB);
    build_P<<<N_, 64>>>(scalB);
    pairwise_mma<<<dim3(MT, MT), 512, PW_SMEM>>>(out);
}